// round 13
// baseline (speedup 1.0000x reference)
#include <cuda_runtime.h>
#include <cuda_bf16.h>
#include <math.h>
#include <stdint.h>

// ---------------- problem constants ----------------
#define BB     4
#define CLID   128
#define HH     256
#define WW     256
#define HWSZ   65536
#define CCAM   256
#define NTOK   8192
#define HDIM   128
#define NHEADS 4
#define MTOT   (BB*NTOK)             // 32768 tokens
#define SCALE  0.17677669529663687f  // 1/sqrt(32)

// ---------------- GEMM tiling ----------------
#define BM 128
#define BN 128
#define BK 32
#define QBM 64          // k_qgemm M-tile (occupancy-optimized)
#define SAW 20          // smem row stride in words, conflict-free
#define NPART 4         // softmax partial blocks per (b,h)
#define NT128 (MTOT/BM) // 256 GEMM tiles
#define CAP 16          // per-pixel token list capacity

// ---------------- scratch (device globals) ----------------
__device__ uint32_t g_k[MTOT*64];            // K [32768][128] bf16 packed
__device__ uint32_t g_v[MTOT*64];            // V [32768][128] bf16 packed
__device__ float    g_y[MTOT*HDIM];          // dense projected deltas (fp32)
__device__ float    g_logit[BB*NHEADS*NTOK];
__device__ float2   g_part[BB*NHEADS*NPART]; // (local max, local sumexp)
__device__ int      g_cnt[BB*HWSZ];          // per-pixel token counts
__device__ int      g_list[BB*HWSZ*CAP];     // per-pixel token lists
__device__ int      g_ovfc;                  // overflow count
__device__ int      g_ovf[MTOT];             // overflow token ids

// ---------------- helpers ----------------
__device__ __forceinline__ uint32_t f2b(float x, float y) {
    __nv_bfloat162 h = __floats2bfloat162_rn(x, y);
    return *reinterpret_cast<uint32_t*>(&h);
}
__device__ __forceinline__ float2 b2f(uint32_t u) {
    __nv_bfloat162 h = *reinterpret_cast<__nv_bfloat162*>(&u);
    return __bfloat1622float2(h);
}

#define MMA(d, a0,a1,a2,a3, b0,b1)                                              \
    asm volatile("mma.sync.aligned.m16n8k16.row.col.f32.bf16.bf16.f32 "         \
                 "{%0,%1,%2,%3},{%4,%5,%6,%7},{%8,%9},{%0,%1,%2,%3};"           \
                 : "+f"(d[0]), "+f"(d[1]), "+f"(d[2]), "+f"(d[3])               \
                 : "r"(a0), "r"(a1), "r"(a2), "r"(a3), "r"(b0), "r"(b1))

// ============================================================
// Kernel 0: zero counts + overflow counter
// ============================================================
__global__ void k_zero()
{
    int i = blockIdx.x * blockDim.x + threadIdx.x;
    ((int4*)g_cnt)[i] = make_int4(0, 0, 0, 0);
    if (i == 0) g_ovfc = 0;
}

// ============================================================
// Kernel 1: bin tokens by destination pixel
// ============================================================
__global__ void k_bin(const int* __restrict__ ind)
{
    int tk = blockIdx.x * blockDim.x + threadIdx.x;
    int b  = tk >> 13;
    int ii = ind[tk * 2 + 0], jj = ind[tk * 2 + 1];
    ii = min(max(ii, 0), HH - 1);
    jj = min(max(jj, 0), WW - 1);
    int bp = b * HWSZ + ii * WW + jj;
    int slot = atomicAdd(&g_cnt[bp], 1);
    if (slot < CAP) g_list[(size_t)bp * CAP + slot] = tk;
    else { int o = atomicAdd(&g_ovfc, 1); g_ovf[o] = tk; }
}

// ============================================================
// Kernel B: K = tok @ k_w^T, V = tok @ v_w^T  (blockIdx.y: 0->K, 1->V)
// bf16 MMA, BM=128, A-tile register-prefetched
// ============================================================
__global__ void __launch_bounds__(256, 2)
k_kv(const float* __restrict__ tok,
     const float* __restrict__ k_w,
     const float* __restrict__ v_w)
{
    __shared__ uint32_t sA[BM * SAW];
    __shared__ uint32_t sB[BN * SAW];

    const int m0 = blockIdx.x * BM;
    const float* w = blockIdx.y ? v_w : k_w;
    uint32_t* outp = blockIdx.y ? g_v : g_k;

    const int tid  = threadIdx.x;
    const int lane = tid & 31, wid = tid >> 5;
    const int wm = (wid & 3) * 32, wn = (wid >> 2) * 64;
    const int g = lane >> 2, t = lane & 3;

    float acc[2][8][4];
#pragma unroll
    for (int i = 0; i < 2; i++)
#pragma unroll
        for (int j = 0; j < 8; j++)
#pragma unroll
            for (int q = 0; q < 4; q++) acc[i][j][q] = 0.f;

    const int ac = tid & 7;
    float4 va[4];
#pragma unroll
    for (int i = 0; i < 4; i++) {
        int row = (tid + i * 256) >> 3;
        va[i] = *(const float4*)(tok + (size_t)(m0 + row) * CCAM + ac * 4);
    }

    for (int k0 = 0; k0 < CCAM; k0 += BK) {
#pragma unroll
        for (int i = 0; i < 4; i++) {
            int row = (tid + i * 256) >> 3;
            sA[row * SAW + ac * 2]     = f2b(va[i].x, va[i].y);
            sA[row * SAW + ac * 2 + 1] = f2b(va[i].z, va[i].w);
        }
#pragma unroll
        for (int i = 0; i < 4; i++) {
            int f = tid + i * 256, row = f >> 3, c = f & 7;
            float4 v = *(const float4*)(w + (size_t)row * CCAM + k0 + c * 4);
            sB[row * SAW + c * 2]     = f2b(v.x, v.y);
            sB[row * SAW + c * 2 + 1] = f2b(v.z, v.w);
        }
        __syncthreads();

        if (k0 + BK < CCAM) {
#pragma unroll
            for (int i = 0; i < 4; i++) {
                int row = (tid + i * 256) >> 3;
                va[i] = *(const float4*)(tok + (size_t)(m0 + row) * CCAM + (k0 + BK) + ac * 4);
            }
        }

#pragma unroll
        for (int kk = 0; kk < 2; kk++) {
            uint32_t br[8][2];
#pragma unroll
            for (int fn = 0; fn < 8; fn++) {
                int n = wn + fn * 8 + g;
                br[fn][0] = sB[n * SAW + kk * 8 + t];
                br[fn][1] = sB[n * SAW + kk * 8 + t + 4];
            }
#pragma unroll
            for (int fm = 0; fm < 2; fm++) {
                int m = wm + fm * 16 + g;
                uint32_t a0 = sA[m * SAW + kk * 8 + t];
                uint32_t a1 = sA[(m + 8) * SAW + kk * 8 + t];
                uint32_t a2 = sA[m * SAW + kk * 8 + t + 4];
                uint32_t a3 = sA[(m + 8) * SAW + kk * 8 + t + 4];
#pragma unroll
                for (int fn = 0; fn < 8; fn++)
                    MMA(acc[fm][fn], a0, a1, a2, a3, br[fn][0], br[fn][1]);
            }
        }
        __syncthreads();
    }

#pragma unroll
    for (int fm = 0; fm < 2; fm++)
#pragma unroll
        for (int fn = 0; fn < 8; fn++) {
            int m = m0 + wm + fm * 16 + g;
            int wcol = (wn >> 1) + fn * 4 + t;
            outp[(size_t)m * 64 + wcol]       = f2b(acc[fm][fn][0], acc[fm][fn][1]);
            outp[(size_t)(m + 8) * 64 + wcol] = f2b(acc[fm][fn][2], acc[fm][fn][3]);
        }
}

// ============================================================
// Kernel C: gathered Q GEMM (BM=64, high occupancy) + fused logit epilogue
// 8 warps, warp grid 2(m) x 4(n); warp tile 32m x 32n (= 1 head per warp)
// ============================================================
__global__ void __launch_bounds__(256, 3)
k_qgemm(const float* __restrict__ lidar,
        const int*   __restrict__ ind,
        const float* __restrict__ q_w,
        const float* __restrict__ q_bias)
{
    __shared__ uint32_t sA[QBM * SAW];
    __shared__ uint32_t sB[BN * SAW];
    __shared__ int spix[QBM];

    const int m0    = blockIdx.x * QBM;
    const int batch = m0 >> 13;
    const int tid   = threadIdx.x;

    if (tid < QBM) {
        int tk = m0 + tid;
        int ii = ind[tk * 2 + 0], jj = ind[tk * 2 + 1];
        ii = min(max(ii, 0), HH - 1);
        jj = min(max(jj, 0), WW - 1);
        spix[tid] = ii * WW + jj;
    }
    __syncthreads();

    const int lane = tid & 31, wid = tid >> 5;
    const int wm = (wid & 1) * 32, wn = (wid >> 1) * 32;
    const int g = lane >> 2, t = lane & 3;

    float acc[2][4][4];
#pragma unroll
    for (int i = 0; i < 2; i++)
#pragma unroll
        for (int j = 0; j < 4; j++)
#pragma unroll
            for (int q = 0; q < 4; q++) acc[i][j][q] = 0.f;

    const float* lb = lidar + (size_t)batch * CLID * HWSZ;

    // hoist gather pixels (k0-invariant): 4 rows per thread
    int mypix[4];
#pragma unroll
    for (int i = 0; i < 4; i++) mypix[i] = spix[(tid + i * 256) >> 4];
    const int p = tid & 15;

    for (int k0 = 0; k0 < CLID; k0 += BK) {
#pragma unroll
        for (int i = 0; i < 4; i++) {           // gather: 64 rows x 16 word-cols
            int row = (tid + i * 256) >> 4;
            const float* lp = lb + (size_t)(k0 + 2 * p) * HWSZ + mypix[i];
            sA[row * SAW + p] = f2b(lp[0], lp[HWSZ]);
        }
#pragma unroll
        for (int i = 0; i < 4; i++) {           // stage q_w (128 x 32 ch)
            int f = tid + i * 256, row = f >> 3, c = f & 7;
            float4 v = *(const float4*)(q_w + (size_t)row * CLID + k0 + c * 4);
            sB[row * SAW + c * 2]     = f2b(v.x, v.y);
            sB[row * SAW + c * 2 + 1] = f2b(v.z, v.w);
        }
        __syncthreads();
#pragma unroll
        for (int kk = 0; kk < 2; kk++) {
            uint32_t br[4][2];
#pragma unroll
            for (int fn = 0; fn < 4; fn++) {
                int n = wn + fn * 8 + g;
                br[fn][0] = sB[n * SAW + kk * 8 + t];
                br[fn][1] = sB[n * SAW + kk * 8 + t + 4];
            }
#pragma unroll
            for (int fm = 0; fm < 2; fm++) {
                int m = wm + fm * 16 + g;
                uint32_t a0 = sA[m * SAW + kk * 8 + t];
                uint32_t a1 = sA[(m + 8) * SAW + kk * 8 + t];
                uint32_t a2 = sA[m * SAW + kk * 8 + t + 4];
                uint32_t a3 = sA[(m + 8) * SAW + kk * 8 + t + 4];
#pragma unroll
                for (int fn = 0; fn < 4; fn++)
                    MMA(acc[fm][fn], a0, a1, a2, a3, br[fn][0], br[fn][1]);
            }
        }
        __syncthreads();
    }

    // fused logit epilogue: each warp owns head h = wn>>5 for its m-rows
    const int h = wn >> 5;
    float* lpo = g_logit + (size_t)(batch * NHEADS + h) * NTOK;
#pragma unroll
    for (int fm = 0; fm < 2; fm++) {
        int m = m0 + wm + fm * 16 + g;
        int tl0 = m & (NTOK - 1), tl1 = (m + 8) & (NTOK - 1);
        float p0 = 0.f, p1 = 0.f;
#pragma unroll
        for (int fn = 0; fn < 4; fn++) {
            int n0 = wn + fn * 8 + 2 * t;
            float2 qb = *(const float2*)(q_bias + n0);
            int word = (wn >> 1) + fn * 4 + t;
            float2 k0v = b2f(g_k[(size_t)m * 64 + word]);
            float2 k1v = b2f(g_k[(size_t)(m + 8) * 64 + word]);
            p0 += (acc[fm][fn][0] + qb.x) * k0v.x + (acc[fm][fn][1] + qb.y) * k0v.y;
            p1 += (acc[fm][fn][2] + qb.x) * k1v.x + (acc[fm][fn][3] + qb.y) * k1v.y;
        }
        p0 += __shfl_xor_sync(0xffffffffu, p0, 1);
        p0 += __shfl_xor_sync(0xffffffffu, p0, 2);
        p1 += __shfl_xor_sync(0xffffffffu, p1, 1);
        p1 += __shfl_xor_sync(0xffffffffu, p1, 2);
        if (t == 0) {
            lpo[tl0] = p0 * SCALE;
            lpo[tl1] = p1 * SCALE;
        }
    }
}

// ============================================================
// Kernel D: per (b,head,part) partial max + sumexp (grid = 64)
// ============================================================
__global__ void __launch_bounds__(256)
k_softred()
{
    const int bx  = blockIdx.x;
    const int bh  = bx >> 2, part = bx & 3;
    const float* lp = g_logit + (size_t)bh * NTOK + part * (NTOK / NPART);
    const int tid = threadIdx.x;
    __shared__ float red[256];

    float v[8];
#pragma unroll
    for (int i = 0; i < 8; i++) v[i] = lp[tid + i * 256];
    float mx = v[0];
#pragma unroll
    for (int i = 1; i < 8; i++) mx = fmaxf(mx, v[i]);
    red[tid] = mx; __syncthreads();
    for (int s = 128; s > 0; s >>= 1) {
        if (tid < s) red[tid] = fmaxf(red[tid], red[tid + s]);
        __syncthreads();
    }
    mx = red[0]; __syncthreads();

    float sum = 0.f;
#pragma unroll
    for (int i = 0; i < 8; i++) sum += expf(v[i] - mx);
    red[tid] = sum; __syncthreads();
    for (int s = 128; s > 0; s >>= 1) {
        if (tid < s) red[tid] += red[tid + s];
        __syncthreads();
    }
    if (tid == 0) g_part[bx] = make_float2(mx, red[0]);
}

// ============================================================
// Kernel E: k_fuse — attn weights; y = out_w @ (attn*V) -> g_y (dense)
// ============================================================
__global__ void __launch_bounds__(256, 2)
k_fuse(const float* __restrict__ gw,
       const float* __restrict__ alpha_p,
       const float* __restrict__ out_w)
{
    __shared__ uint32_t sA[BM * SAW];
    __shared__ uint32_t sB[BN * SAW];
    __shared__ float  saw_[BM * NHEADS];
    __shared__ float2 sred[NHEADS];

    const int m0    = blockIdx.x * BM;
    const int batch = m0 >> 13;
    const int tid   = threadIdx.x;

    if (tid < NHEADS) {
        int bh = batch * NHEADS + tid;
        float2 p[NPART];
#pragma unroll
        for (int i = 0; i < NPART; i++) p[i] = g_part[bh * NPART + i];
        float mx = p[0].x;
#pragma unroll
        for (int i = 1; i < NPART; i++) mx = fmaxf(mx, p[i].x);
        float sum = 0.f;
#pragma unroll
        for (int i = 0; i < NPART; i++) sum += p[i].y * expf(p[i].x - mx);
        sred[tid] = make_float2(mx, 1.0f / sum);
    }
    __syncthreads();
    {
        float alpha = *alpha_p;
#pragma unroll
        for (int j = 0; j < 2; j++) {
            int idx = tid + j * 256;
            int tl = idx & 127, h = idx >> 7;
            int tloc = (m0 & (NTOK - 1)) + tl;
            float  lt = g_logit[(size_t)(batch * NHEADS + h) * NTOK + tloc];
            float2 r  = sred[h];
            saw_[tl * NHEADS + h] = expf(lt - r.x) * r.y * gw[(size_t)batch * NTOK + tloc] * alpha;
        }
    }
    __syncthreads();

    const int lane = tid & 31, wid = tid >> 5;
    const int wm = (wid & 3) * 32, wn = (wid >> 2) * 64;
    const int g = lane >> 2, t = lane & 3;

    float acc[2][8][4];
#pragma unroll
    for (int i = 0; i < 2; i++)
#pragma unroll
        for (int j = 0; j < 8; j++)
#pragma unroll
            for (int q = 0; q < 4; q++) acc[i][j][q] = 0.f;

    for (int k0 = 0; k0 < HDIM; k0 += BK) {
#pragma unroll
        for (int i = 0; i < 8; i++) {
            int f = tid + i * 256, row = f >> 4, wc = f & 15;
            uint32_t u = g_v[(size_t)(m0 + row) * 64 + (k0 >> 1) + wc];
            float2 v = b2f(u);
            int h = (k0 + 2 * wc) >> 5;
            float wgt = saw_[row * NHEADS + h];
            sA[row * SAW + wc] = f2b(v.x * wgt, v.y * wgt);
        }
#pragma unroll
        for (int i = 0; i < 4; i++) {
            int f = tid + i * 256, row = f >> 3, c = f & 7;
            float4 v = *(const float4*)(out_w + (size_t)row * HDIM + k0 + c * 4);
            sB[row * SAW + c * 2]     = f2b(v.x, v.y);
            sB[row * SAW + c * 2 + 1] = f2b(v.z, v.w);
        }
        __syncthreads();
#pragma unroll
        for (int kk = 0; kk < 2; kk++) {
            uint32_t br[8][2];
#pragma unroll
            for (int fn = 0; fn < 8; fn++) {
                int n = wn + fn * 8 + g;
                br[fn][0] = sB[n * SAW + kk * 8 + t];
                br[fn][1] = sB[n * SAW + kk * 8 + t + 4];
            }
#pragma unroll
            for (int fm = 0; fm < 2; fm++) {
                int m = wm + fm * 16 + g;
                uint32_t a0 = sA[m * SAW + kk * 8 + t];
                uint32_t a1 = sA[(m + 8) * SAW + kk * 8 + t];
                uint32_t a2 = sA[m * SAW + kk * 8 + t + 4];
                uint32_t a3 = sA[(m + 8) * SAW + kk * 8 + t + 4];
#pragma unroll
                for (int fn = 0; fn < 8; fn++)
                    MMA(acc[fm][fn], a0, a1, a2, a3, br[fn][0], br[fn][1]);
            }
        }
        __syncthreads();
    }

#pragma unroll
    for (int fm = 0; fm < 2; fm++) {
        int m = m0 + wm + fm * 16 + g;
#pragma unroll
        for (int fn = 0; fn < 8; fn++) {
            int col = wn + fn * 8 + 2 * t;
            *(float2*)(g_y + (size_t)m * HDIM + col) =
                make_float2(acc[fm][fn][0], acc[fm][fn][1]);
            *(float2*)(g_y + (size_t)(m + 8) * HDIM + col) =
                make_float2(acc[fm][fn][2], acc[fm][fn][3]);
        }
    }
}

// ============================================================
// Kernel F: k_finalize — dense output pass, no atomics
// ============================================================
__global__ void __launch_bounds__(256)
k_finalize(const float* __restrict__ lidar,
           const float* __restrict__ alpha_p,
           const float* __restrict__ out_bias,
           float* __restrict__ out)
{
    __shared__ float sacc[32 * 129];
    __shared__ int   swork[32 * CAP];
    __shared__ int   stot;

    const int b   = blockIdx.x >> 11;
    const int p0  = (blockIdx.x & 2047) * 32;
    const int tid = threadIdx.x;

    for (int i = tid; i < 32 * 129; i += 256) sacc[i] = 0.f;

    if (tid < 32) {
        int px  = tid;
        int cnt = min(g_cnt[b * HWSZ + p0 + px], CAP);
        int inc = cnt;
#pragma unroll
        for (int d = 1; d < 32; d <<= 1) {
            int n = __shfl_up_sync(0xffffffffu, inc, d);
            if (px >= d) inc += n;
        }
        int excl = inc - cnt;
        if (px == 31) stot = inc;
        for (int i = 0; i < cnt; i++)
            swork[excl + i] = (px << 20) | g_list[(size_t)(b * HWSZ + p0 + px) * CAP + i];
    }
    __syncthreads();

    const int total = stot;
    for (int w = (tid >> 7); w < total; w += 2) {
        int e  = swork[w];
        int px = e >> 20, tk = e & 0xFFFFF;
        int c  = tid & 127;
        atomicAdd(&sacc[px * 129 + c], g_y[(size_t)tk * HDIM + c]);
    }
    __syncthreads();

    const float alpha = *alpha_p;
#pragma unroll
    for (int j = 0; j < 16; j++) {
        int lin = tid + j * 256;
        int c = lin >> 5, px = lin & 31;
        size_t gi = ((size_t)b * CLID + c) * HWSZ + p0 + px;
        out[gi] = lidar[gi] + alpha * out_bias[c] + sacc[px * 129 + c];
    }
}

// ============================================================
// Kernel G: k_ovf — overflow tokens (grid-stride; normally zero work)
// ============================================================
__global__ void __launch_bounds__(256)
k_ovf(const int* __restrict__ ind,
      float* __restrict__ out)
{
    __shared__ int scnt;
    if (threadIdx.x == 0) scnt = g_ovfc;
    __syncthreads();
    const int nw = scnt * 8;   // 8 thread-chunks per overflow token
    for (int idx = blockIdx.x * 256 + threadIdx.x; idx < nw; idx += 32 * 256) {
        int o  = idx >> 3;
        int tk = g_ovf[o];
        int c0 = (idx & 7) * 16;
        int b  = tk >> 13;
        int ii = ind[tk * 2 + 0], jj = ind[tk * 2 + 1];
        ii = min(max(ii, 0), HH - 1);
        jj = min(max(jj, 0), WW - 1);
        int pix = ii * WW + jj;
        const float* yp = g_y + (size_t)tk * HDIM + c0;
        float* ob = out + (size_t)b * CLID * HWSZ + (size_t)c0 * HWSZ + pix;
#pragma unroll
        for (int c = 0; c < 16; c++)
            atomicAdd(ob + (size_t)c * HWSZ, yp[c]);
    }
}

// ============================================================
extern "C" void kernel_launch(void* const* d_in, const int* in_sizes, int n_in,
                              void* d_out, int out_size)
{
    const float* lidar = (const float*)d_in[0];
    const float* tok   = (const float*)d_in[1];
    const int*   ind   = (const int*)  d_in[2];
    const float* gw    = (const float*)d_in[3];
    const float* alpha = (const float*)d_in[4];
    const float* q_w   = (const float*)d_in[5];
    const float* q_b   = (const float*)d_in[6];
    const float* k_w   = (const float*)d_in[7];
    const float* v_w   = (const float*)d_in[8];
    const float* o_w   = (const float*)d_in[9];
    const float* o_b   = (const float*)d_in[10];
    float* out = (float*)d_out;

    k_zero<<<BB * HWSZ / 4 / 256, 256>>>();
    k_bin<<<MTOT / 256, 256>>>(ind);
    dim3 gb(NT128, 2);
    k_kv<<<gb, 256>>>(tok, k_w, v_w);
    k_qgemm<<<MTOT / QBM, 256>>>(lidar, ind, q_w, q_b);
    k_softred<<<BB * NHEADS * NPART, 256>>>();
    k_fuse<<<NT128, 256>>>(gw, alpha, o_w);
    k_finalize<<<BB * HWSZ / 32, 256>>>(lidar, alpha, o_b, out);
    k_ovf<<<32, 256>>>(ind, out);
}

// round 15
// speedup vs baseline: 1.0257x; 1.0257x over previous
#include <cuda_runtime.h>
#include <cuda_bf16.h>
#include <math.h>
#include <stdint.h>

// ---------------- problem constants ----------------
#define BB     4
#define CLID   128
#define HH     256
#define WW     256
#define HWSZ   65536
#define CCAM   256
#define NTOK   8192
#define HDIM   128
#define NHEADS 4
#define MTOT   (BB*NTOK)             // 32768 tokens
#define SCALE  0.17677669529663687f  // 1/sqrt(32)

// ---------------- GEMM tiling ----------------
#define BM 128
#define BN 128
#define BK 32
#define SAW 20          // smem row stride in words, conflict-free
#define NPART 4         // softmax partial blocks per (b,h)
#define NT128 (MTOT/BM) // 256 GEMM tiles
#define CAP 16          // per-pixel token list capacity
#define QGRID (NT128/2) // qgemm: 128 blocks x 2 tiles (L2 working-set cap)

// ---------------- scratch (device globals) ----------------
__device__ uint32_t g_k[MTOT*64];            // K [32768][128] bf16 packed
__device__ uint32_t g_v[MTOT*64];            // V [32768][128] bf16 packed
__device__ float    g_y[MTOT*HDIM];          // dense projected deltas (fp32)
__device__ float    g_logit[BB*NHEADS*NTOK];
__device__ float2   g_part[BB*NHEADS*NPART]; // (local max, local sumexp)
__device__ int      g_cnt[BB*HWSZ];          // per-pixel token counts
__device__ int      g_list[BB*HWSZ*CAP];     // per-pixel token lists
__device__ int      g_ovfc;                  // overflow count
__device__ int      g_ovf[MTOT];             // overflow token ids

// ---------------- helpers ----------------
__device__ __forceinline__ uint32_t f2b(float x, float y) {
    __nv_bfloat162 h = __floats2bfloat162_rn(x, y);
    return *reinterpret_cast<uint32_t*>(&h);
}
__device__ __forceinline__ float2 b2f(uint32_t u) {
    __nv_bfloat162 h = *reinterpret_cast<__nv_bfloat162*>(&u);
    return __bfloat1622float2(h);
}

#define MMA(d, a0,a1,a2,a3, b0,b1)                                              \
    asm volatile("mma.sync.aligned.m16n8k16.row.col.f32.bf16.bf16.f32 "         \
                 "{%0,%1,%2,%3},{%4,%5,%6,%7},{%8,%9},{%0,%1,%2,%3};"           \
                 : "+f"(d[0]), "+f"(d[1]), "+f"(d[2]), "+f"(d[3])               \
                 : "r"(a0), "r"(a1), "r"(a2), "r"(a3), "r"(b0), "r"(b1))

// 256 threads = 8 warps, warp grid 4(m) x 2(n); warp tile 32m x 64n

// ============================================================
// Kernel 0: zero counts + overflow counter
// ============================================================
__global__ void k_zero()
{
    int i = blockIdx.x * blockDim.x + threadIdx.x;
    ((int4*)g_cnt)[i] = make_int4(0, 0, 0, 0);
    if (i == 0) g_ovfc = 0;
}

// ============================================================
// Kernel 1: bin tokens by destination pixel
// ============================================================
__global__ void k_bin(const int* __restrict__ ind)
{
    int tk = blockIdx.x * blockDim.x + threadIdx.x;
    int b  = tk >> 13;
    int ii = ind[tk * 2 + 0], jj = ind[tk * 2 + 1];
    ii = min(max(ii, 0), HH - 1);
    jj = min(max(jj, 0), WW - 1);
    int bp = b * HWSZ + ii * WW + jj;
    int slot = atomicAdd(&g_cnt[bp], 1);
    if (slot < CAP) g_list[(size_t)bp * CAP + slot] = tk;
    else { int o = atomicAdd(&g_ovfc, 1); g_ovf[o] = tk; }
}

// ============================================================
// Kernel B: K = tok @ k_w^T, V = tok @ v_w^T  (blockIdx.y: 0->K, 1->V)
// bf16 MMA, BM=128, A-tile register-prefetched
// ============================================================
__global__ void __launch_bounds__(256, 2)
k_kv(const float* __restrict__ tok,
     const float* __restrict__ k_w,
     const float* __restrict__ v_w)
{
    __shared__ uint32_t sA[BM * SAW];
    __shared__ uint32_t sB[BN * SAW];

    const int m0 = blockIdx.x * BM;
    const float* w = blockIdx.y ? v_w : k_w;
    uint32_t* outp = blockIdx.y ? g_v : g_k;

    const int tid  = threadIdx.x;
    const int lane = tid & 31, wid = tid >> 5;
    const int wm = (wid & 3) * 32, wn = (wid >> 2) * 64;
    const int g = lane >> 2, t = lane & 3;

    float acc[2][8][4];
#pragma unroll
    for (int i = 0; i < 2; i++)
#pragma unroll
        for (int j = 0; j < 8; j++)
#pragma unroll
            for (int q = 0; q < 4; q++) acc[i][j][q] = 0.f;

    const int ac = tid & 7;
    float4 va[4];
#pragma unroll
    for (int i = 0; i < 4; i++) {
        int row = (tid + i * 256) >> 3;
        va[i] = *(const float4*)(tok + (size_t)(m0 + row) * CCAM + ac * 4);
    }

    for (int k0 = 0; k0 < CCAM; k0 += BK) {
#pragma unroll
        for (int i = 0; i < 4; i++) {
            int row = (tid + i * 256) >> 3;
            sA[row * SAW + ac * 2]     = f2b(va[i].x, va[i].y);
            sA[row * SAW + ac * 2 + 1] = f2b(va[i].z, va[i].w);
        }
#pragma unroll
        for (int i = 0; i < 4; i++) {
            int f = tid + i * 256, row = f >> 3, c = f & 7;
            float4 v = *(const float4*)(w + (size_t)row * CCAM + k0 + c * 4);
            sB[row * SAW + c * 2]     = f2b(v.x, v.y);
            sB[row * SAW + c * 2 + 1] = f2b(v.z, v.w);
        }
        __syncthreads();

        if (k0 + BK < CCAM) {
#pragma unroll
            for (int i = 0; i < 4; i++) {
                int row = (tid + i * 256) >> 3;
                va[i] = *(const float4*)(tok + (size_t)(m0 + row) * CCAM + (k0 + BK) + ac * 4);
            }
        }

#pragma unroll
        for (int kk = 0; kk < 2; kk++) {
            uint32_t br[8][2];
#pragma unroll
            for (int fn = 0; fn < 8; fn++) {
                int n = wn + fn * 8 + g;
                br[fn][0] = sB[n * SAW + kk * 8 + t];
                br[fn][1] = sB[n * SAW + kk * 8 + t + 4];
            }
#pragma unroll
            for (int fm = 0; fm < 2; fm++) {
                int m = wm + fm * 16 + g;
                uint32_t a0 = sA[m * SAW + kk * 8 + t];
                uint32_t a1 = sA[(m + 8) * SAW + kk * 8 + t];
                uint32_t a2 = sA[m * SAW + kk * 8 + t + 4];
                uint32_t a3 = sA[(m + 8) * SAW + kk * 8 + t + 4];
#pragma unroll
                for (int fn = 0; fn < 8; fn++)
                    MMA(acc[fm][fn], a0, a1, a2, a3, br[fn][0], br[fn][1]);
            }
        }
        __syncthreads();
    }

#pragma unroll
    for (int fm = 0; fm < 2; fm++)
#pragma unroll
        for (int fn = 0; fn < 8; fn++) {
            int m = m0 + wm + fm * 16 + g;
            int wcol = (wn >> 1) + fn * 4 + t;
            outp[(size_t)m * 64 + wcol]       = f2b(acc[fm][fn][0], acc[fm][fn][1]);
            outp[(size_t)(m + 8) * 64 + wcol] = f2b(acc[fm][fn][2], acc[fm][fn][3]);
        }
}

// ============================================================
// Kernel C: gathered Q GEMM + fused logit epilogue.
// Grid = 128; block processes tile blk, then tile blk+128.
// Phase 0 = batches {0,1}, phase 1 = batches {2,3}: concurrent lidar
// working set 67 MB < L2, so gather sector amplification hits L2 not DRAM.
// ============================================================
__global__ void __launch_bounds__(256)
k_qgemm(const float* __restrict__ lidar,
        const int*   __restrict__ ind,
        const float* __restrict__ q_w,
        const float* __restrict__ q_bias)
{
    __shared__ uint32_t sA[BM * SAW];
    __shared__ uint32_t sB[BN * SAW];
    __shared__ int spix[BM];

    const int tid = threadIdx.x;
    const int lane = tid & 31, wid = tid >> 5;
    const int wm = (wid & 3) * 32, wn = (wid >> 2) * 64;
    const int g = lane >> 2, t = lane & 3;

    for (int it = 0; it < 2; it++) {
        const int m0    = (blockIdx.x + it * QGRID) * BM;
        const int batch = m0 >> 13;

        if (tid < BM) {
            int tk = m0 + tid;
            int ii = ind[tk * 2 + 0], jj = ind[tk * 2 + 1];
            ii = min(max(ii, 0), HH - 1);
            jj = min(max(jj, 0), WW - 1);
            spix[tid] = ii * WW + jj;
        }
        __syncthreads();

        float acc[2][8][4];
#pragma unroll
        for (int i = 0; i < 2; i++)
#pragma unroll
            for (int j = 0; j < 8; j++)
#pragma unroll
                for (int q = 0; q < 4; q++) acc[i][j][q] = 0.f;

        const float* lb = lidar + (size_t)batch * CLID * HWSZ;

        // hoist gather pixels (k0-invariant)
        int mypix[8];
#pragma unroll
        for (int i = 0; i < 8; i++) mypix[i] = spix[(tid + i * 256) >> 4];
        const int p = tid & 15;

        for (int k0 = 0; k0 < CLID; k0 += BK) {
#pragma unroll
            for (int i = 0; i < 8; i++) {           // gather stage
                int row = (tid + i * 256) >> 4;
                const float* lp = lb + (size_t)(k0 + 2 * p) * HWSZ + mypix[i];
                sA[row * SAW + p] = f2b(lp[0], lp[HWSZ]);
            }
#pragma unroll
            for (int i = 0; i < 4; i++) {           // stage q_w
                int f = tid + i * 256, row = f >> 3, c = f & 7;
                float4 v = *(const float4*)(q_w + (size_t)row * CLID + k0 + c * 4);
                sB[row * SAW + c * 2]     = f2b(v.x, v.y);
                sB[row * SAW + c * 2 + 1] = f2b(v.z, v.w);
            }
            __syncthreads();
#pragma unroll
            for (int kk = 0; kk < 2; kk++) {
                uint32_t br[8][2];
#pragma unroll
                for (int fn = 0; fn < 8; fn++) {
                    int n = wn + fn * 8 + g;
                    br[fn][0] = sB[n * SAW + kk * 8 + t];
                    br[fn][1] = sB[n * SAW + kk * 8 + t + 4];
                }
#pragma unroll
                for (int fm = 0; fm < 2; fm++) {
                    int m = wm + fm * 16 + g;
                    uint32_t a0 = sA[m * SAW + kk * 8 + t];
                    uint32_t a1 = sA[(m + 8) * SAW + kk * 8 + t];
                    uint32_t a2 = sA[m * SAW + kk * 8 + t + 4];
                    uint32_t a3 = sA[(m + 8) * SAW + kk * 8 + t + 4];
#pragma unroll
                    for (int fn = 0; fn < 8; fn++)
                        MMA(acc[fm][fn], a0, a1, a2, a3, br[fn][0], br[fn][1]);
                }
            }
            __syncthreads();
        }

        // fused logit epilogue (no smem reads; safe vs next iter's spix write)
#pragma unroll
        for (int fm = 0; fm < 2; fm++) {
            int m = m0 + wm + fm * 16 + g;
            int tl0 = m & (NTOK - 1), tl1 = (m + 8) & (NTOK - 1);
#pragma unroll
            for (int hoff = 0; hoff < 2; hoff++) {
                float p0 = 0.f, p1 = 0.f;
#pragma unroll
                for (int fn2 = 0; fn2 < 4; fn2++) {
                    int fn = hoff * 4 + fn2;
                    int n0 = wn + fn * 8 + 2 * t;
                    float2 qb = *(const float2*)(q_bias + n0);
                    int word = (wn >> 1) + hoff * 16 + fn2 * 4 + t;
                    float2 k0v = b2f(g_k[(size_t)m * 64 + word]);
                    float2 k1v = b2f(g_k[(size_t)(m + 8) * 64 + word]);
                    p0 += (acc[fm][fn][0] + qb.x) * k0v.x + (acc[fm][fn][1] + qb.y) * k0v.y;
                    p1 += (acc[fm][fn][2] + qb.x) * k1v.x + (acc[fm][fn][3] + qb.y) * k1v.y;
                }
                p0 += __shfl_xor_sync(0xffffffffu, p0, 1);
                p0 += __shfl_xor_sync(0xffffffffu, p0, 2);
                p1 += __shfl_xor_sync(0xffffffffu, p1, 1);
                p1 += __shfl_xor_sync(0xffffffffu, p1, 2);
                if (t == 0) {
                    int h = (wn >> 5) + hoff;
                    float* lpo = g_logit + (size_t)(batch * NHEADS + h) * NTOK;
                    lpo[tl0] = p0 * SCALE;
                    lpo[tl1] = p1 * SCALE;
                }
            }
        }
        __syncthreads();
    }
}

// ============================================================
// Kernel D: per (b,head,part) partial max + sumexp (grid = 64)
// ============================================================
__global__ void __launch_bounds__(256)
k_softred()
{
    const int bx  = blockIdx.x;
    const int bh  = bx >> 2, part = bx & 3;
    const float* lp = g_logit + (size_t)bh * NTOK + part * (NTOK / NPART);
    const int tid = threadIdx.x;
    __shared__ float red[256];

    float v[8];
#pragma unroll
    for (int i = 0; i < 8; i++) v[i] = lp[tid + i * 256];
    float mx = v[0];
#pragma unroll
    for (int i = 1; i < 8; i++) mx = fmaxf(mx, v[i]);
    red[tid] = mx; __syncthreads();
    for (int s = 128; s > 0; s >>= 1) {
        if (tid < s) red[tid] = fmaxf(red[tid], red[tid + s]);
        __syncthreads();
    }
    mx = red[0]; __syncthreads();

    float sum = 0.f;
#pragma unroll
    for (int i = 0; i < 8; i++) sum += expf(v[i] - mx);
    red[tid] = sum; __syncthreads();
    for (int s = 128; s > 0; s >>= 1) {
        if (tid < s) red[tid] += red[tid + s];
        __syncthreads();
    }
    if (tid == 0) g_part[bx] = make_float2(mx, red[0]);
}

// ============================================================
// Kernel E: k_fuse — attn weights; y = out_w @ (attn*V) -> g_y (dense)
// ============================================================
__global__ void __launch_bounds__(256, 2)
k_fuse(const float* __restrict__ gw,
       const float* __restrict__ alpha_p,
       const float* __restrict__ out_w)
{
    __shared__ uint32_t sA[BM * SAW];
    __shared__ uint32_t sB[BN * SAW];
    __shared__ float  saw_[BM * NHEADS];
    __shared__ float2 sred[NHEADS];

    const int m0    = blockIdx.x * BM;
    const int batch = m0 >> 13;
    const int tid   = threadIdx.x;

    if (tid < NHEADS) {
        int bh = batch * NHEADS + tid;
        float2 p[NPART];
#pragma unroll
        for (int i = 0; i < NPART; i++) p[i] = g_part[bh * NPART + i];
        float mx = p[0].x;
#pragma unroll
        for (int i = 1; i < NPART; i++) mx = fmaxf(mx, p[i].x);
        float sum = 0.f;
#pragma unroll
        for (int i = 0; i < NPART; i++) sum += p[i].y * expf(p[i].x - mx);
        sred[tid] = make_float2(mx, 1.0f / sum);
    }
    __syncthreads();
    {
        float alpha = *alpha_p;
#pragma unroll
        for (int j = 0; j < 2; j++) {
            int idx = tid + j * 256;
            int tl = idx & 127, h = idx >> 7;
            int tloc = (m0 & (NTOK - 1)) + tl;
            float  lt = g_logit[(size_t)(batch * NHEADS + h) * NTOK + tloc];
            float2 r  = sred[h];
            saw_[tl * NHEADS + h] = expf(lt - r.x) * r.y * gw[(size_t)batch * NTOK + tloc] * alpha;
        }
    }
    __syncthreads();

    const int lane = tid & 31, wid = tid >> 5;
    const int wm = (wid & 3) * 32, wn = (wid >> 2) * 64;
    const int g = lane >> 2, t = lane & 3;

    float acc[2][8][4];
#pragma unroll
    for (int i = 0; i < 2; i++)
#pragma unroll
        for (int j = 0; j < 8; j++)
#pragma unroll
            for (int q = 0; q < 4; q++) acc[i][j][q] = 0.f;

    for (int k0 = 0; k0 < HDIM; k0 += BK) {
#pragma unroll
        for (int i = 0; i < 8; i++) {
            int f = tid + i * 256, row = f >> 4, wc = f & 15;
            uint32_t u = g_v[(size_t)(m0 + row) * 64 + (k0 >> 1) + wc];
            float2 v = b2f(u);
            int h = (k0 + 2 * wc) >> 5;
            float wgt = saw_[row * NHEADS + h];
            sA[row * SAW + wc] = f2b(v.x * wgt, v.y * wgt);
        }
#pragma unroll
        for (int i = 0; i < 4; i++) {
            int f = tid + i * 256, row = f >> 3, c = f & 7;
            float4 v = *(const float4*)(out_w + (size_t)row * HDIM + k0 + c * 4);
            sB[row * SAW + c * 2]     = f2b(v.x, v.y);
            sB[row * SAW + c * 2 + 1] = f2b(v.z, v.w);
        }
        __syncthreads();
#pragma unroll
        for (int kk = 0; kk < 2; kk++) {
            uint32_t br[8][2];
#pragma unroll
            for (int fn = 0; fn < 8; fn++) {
                int n = wn + fn * 8 + g;
                br[fn][0] = sB[n * SAW + kk * 8 + t];
                br[fn][1] = sB[n * SAW + kk * 8 + t + 4];
            }
#pragma unroll
            for (int fm = 0; fm < 2; fm++) {
                int m = wm + fm * 16 + g;
                uint32_t a0 = sA[m * SAW + kk * 8 + t];
                uint32_t a1 = sA[(m + 8) * SAW + kk * 8 + t];
                uint32_t a2 = sA[m * SAW + kk * 8 + t + 4];
                uint32_t a3 = sA[(m + 8) * SAW + kk * 8 + t + 4];
#pragma unroll
                for (int fn = 0; fn < 8; fn++)
                    MMA(acc[fm][fn], a0, a1, a2, a3, br[fn][0], br[fn][1]);
            }
        }
        __syncthreads();
    }

#pragma unroll
    for (int fm = 0; fm < 2; fm++) {
        int m = m0 + wm + fm * 16 + g;
#pragma unroll
        for (int fn = 0; fn < 8; fn++) {
            int col = wn + fn * 8 + 2 * t;
            *(float2*)(g_y + (size_t)m * HDIM + col) =
                make_float2(acc[fm][fn][0], acc[fm][fn][1]);
            *(float2*)(g_y + (size_t)(m + 8) * HDIM + col) =
                make_float2(acc[fm][fn][2], acc[fm][fn][3]);
        }
    }
}

// ============================================================
// Kernel F: k_finalize — dense output pass, no atomics
// ============================================================
__global__ void __launch_bounds__(256)
k_finalize(const float* __restrict__ lidar,
           const float* __restrict__ alpha_p,
           const float* __restrict__ out_bias,
           float* __restrict__ out)
{
    __shared__ float sacc[32 * 129];
    __shared__ int   swork[32 * CAP];
    __shared__ int   stot;

    const int b   = blockIdx.x >> 11;
    const int p0  = (blockIdx.x & 2047) * 32;
    const int tid = threadIdx.x;

    for (int i = tid; i < 32 * 129; i += 256) sacc[i] = 0.f;

    if (tid < 32) {
        int px  = tid;
        int cnt = min(g_cnt[b * HWSZ + p0 + px], CAP);
        int inc = cnt;
#pragma unroll
        for (int d = 1; d < 32; d <<= 1) {
            int n = __shfl_up_sync(0xffffffffu, inc, d);
            if (px >= d) inc += n;
        }
        int excl = inc - cnt;
        if (px == 31) stot = inc;
        for (int i = 0; i < cnt; i++)
            swork[excl + i] = (px << 20) | g_list[(size_t)(b * HWSZ + p0 + px) * CAP + i];
    }
    __syncthreads();

    const int total = stot;
    for (int w = (tid >> 7); w < total; w += 2) {
        int e  = swork[w];
        int px = e >> 20, tk = e & 0xFFFFF;
        int c  = tid & 127;
        atomicAdd(&sacc[px * 129 + c], g_y[(size_t)tk * HDIM + c]);
    }
    __syncthreads();

    const float alpha = *alpha_p;
#pragma unroll
    for (int j = 0; j < 16; j++) {
        int lin = tid + j * 256;
        int c = lin >> 5, px = lin & 31;
        size_t gi = ((size_t)b * CLID + c) * HWSZ + p0 + px;
        out[gi] = lidar[gi] + alpha * out_bias[c] + sacc[px * 129 + c];
    }
}

// ============================================================
// Kernel G: k_ovf — overflow tokens (grid-stride; normally zero work)
// ============================================================
__global__ void __launch_bounds__(256)
k_ovf(const int* __restrict__ ind,
      float* __restrict__ out)
{
    __shared__ int scnt;
    if (threadIdx.x == 0) scnt = g_ovfc;
    __syncthreads();
    const int nw = scnt * 8;
    for (int idx = blockIdx.x * 256 + threadIdx.x; idx < nw; idx += 32 * 256) {
        int o  = idx >> 3;
        int tk = g_ovf[o];
        int c0 = (idx & 7) * 16;
        int b  = tk >> 13;
        int ii = ind[tk * 2 + 0], jj = ind[tk * 2 + 1];
        ii = min(max(ii, 0), HH - 1);
        jj = min(max(jj, 0), WW - 1);
        int pix = ii * WW + jj;
        const float* yp = g_y + (size_t)tk * HDIM + c0;
        float* ob = out + (size_t)b * CLID * HWSZ + (size_t)c0 * HWSZ + pix;
#pragma unroll
        for (int c = 0; c < 16; c++)
            atomicAdd(ob + (size_t)c * HWSZ, yp[c]);
    }
}

// ============================================================
extern "C" void kernel_launch(void* const* d_in, const int* in_sizes, int n_in,
                              void* d_out, int out_size)
{
    const float* lidar = (const float*)d_in[0];
    const float* tok   = (const float*)d_in[1];
    const int*   ind   = (const int*)  d_in[2];
    const float* gw    = (const float*)d_in[3];
    const float* alpha = (const float*)d_in[4];
    const float* q_w   = (const float*)d_in[5];
    const float* q_b   = (const float*)d_in[6];
    const float* k_w   = (const float*)d_in[7];
    const float* v_w   = (const float*)d_in[8];
    const float* o_w   = (const float*)d_in[9];
    const float* o_b   = (const float*)d_in[10];
    float* out = (float*)d_out;

    k_zero<<<BB * HWSZ / 4 / 256, 256>>>();
    k_bin<<<MTOT / 256, 256>>>(ind);
    dim3 gb(NT128, 2);
    k_kv<<<gb, 256>>>(tok, k_w, v_w);
    k_qgemm<<<QGRID, 256>>>(lidar, ind, q_w, q_b);
    k_softred<<<BB * NHEADS * NPART, 256>>>();
    k_fuse<<<NT128, 256>>>(gw, alpha, o_w);
    k_finalize<<<BB * HWSZ / 32, 256>>>(lidar, alpha, o_b, out);
    k_ovf<<<32, 256>>>(ind, out);
}

// round 16
// speedup vs baseline: 1.0775x; 1.0506x over previous
#include <cuda_runtime.h>
#include <cuda_bf16.h>
#include <math.h>
#include <stdint.h>

// ---------------- problem constants ----------------
#define BB     4
#define CLID   128
#define HH     256
#define WW     256
#define HWSZ   65536
#define CCAM   256
#define NTOK   8192
#define HDIM   128
#define NHEADS 4
#define MTOT   (BB*NTOK)             // 32768 tokens
#define SCALE  0.17677669529663687f  // 1/sqrt(32)

// ---------------- GEMM tiling ----------------
#define BM 128
#define BN 128
#define BK 32
#define SAW 20          // smem row stride in words, conflict-free
#define NPART 4         // softmax partial blocks per (b,h)
#define NT128 (MTOT/BM) // 256 GEMM tiles
#define CAP 16          // per-pixel token list capacity

// ---------------- scratch (device globals) ----------------
__device__ uint32_t g_k[MTOT*64];            // K [32768][128] bf16 packed
__device__ uint32_t g_v[MTOT*64];            // V [32768][128] bf16 packed
__device__ float    g_y[MTOT*HDIM];          // dense projected deltas (fp32)
__device__ float    g_logit[BB*NHEADS*NTOK];
__device__ float2   g_part[BB*NHEADS*NPART]; // (local max, local sumexp)
__device__ int      g_cnt[BB*HWSZ];          // per-pixel token counts
__device__ int      g_list[BB*HWSZ*CAP];     // per-pixel token lists
__device__ int      g_ovfc;                  // overflow count
__device__ int      g_ovf[MTOT];             // overflow token ids

// ---------------- helpers ----------------
__device__ __forceinline__ uint32_t f2b(float x, float y) {
    __nv_bfloat162 h = __floats2bfloat162_rn(x, y);
    return *reinterpret_cast<uint32_t*>(&h);
}
__device__ __forceinline__ float2 b2f(uint32_t u) {
    __nv_bfloat162 h = *reinterpret_cast<__nv_bfloat162*>(&u);
    return __bfloat1622float2(h);
}

#define MMA(d, a0,a1,a2,a3, b0,b1)                                              \
    asm volatile("mma.sync.aligned.m16n8k16.row.col.f32.bf16.bf16.f32 "         \
                 "{%0,%1,%2,%3},{%4,%5,%6,%7},{%8,%9},{%0,%1,%2,%3};"           \
                 : "+f"(d[0]), "+f"(d[1]), "+f"(d[2]), "+f"(d[3])               \
                 : "r"(a0), "r"(a1), "r"(a2), "r"(a3), "r"(b0), "r"(b1))

// ============================================================
// Kernel 0: zero counts + overflow counter
// ============================================================
__global__ void k_zero()
{
    int i = blockIdx.x * blockDim.x + threadIdx.x;
    ((int4*)g_cnt)[i] = make_int4(0, 0, 0, 0);
    if (i == 0) g_ovfc = 0;
}

// ============================================================
// Kernel 1: bin tokens by destination pixel
// ============================================================
__global__ void k_bin(const int* __restrict__ ind)
{
    int tk = blockIdx.x * blockDim.x + threadIdx.x;
    int b  = tk >> 13;
    int ii = ind[tk * 2 + 0], jj = ind[tk * 2 + 1];
    ii = min(max(ii, 0), HH - 1);
    jj = min(max(jj, 0), WW - 1);
    int bp = b * HWSZ + ii * WW + jj;
    int slot = atomicAdd(&g_cnt[bp], 1);
    if (slot < CAP) g_list[(size_t)bp * CAP + slot] = tk;
    else { int o = atomicAdd(&g_ovfc, 1); g_ovf[o] = tk; }
}

// ============================================================
// Kernel B: K = tok @ k_w^T, V = tok @ v_w^T  (blockIdx.y: 0->K, 1->V)
// bf16 MMA, BM=128, A-tile register-prefetched  (R11 config, 256 thr)
// ============================================================
__global__ void __launch_bounds__(256, 2)
k_kv(const float* __restrict__ tok,
     const float* __restrict__ k_w,
     const float* __restrict__ v_w)
{
    __shared__ uint32_t sA[BM * SAW];
    __shared__ uint32_t sB[BN * SAW];

    const int m0 = blockIdx.x * BM;
    const float* w = blockIdx.y ? v_w : k_w;
    uint32_t* outp = blockIdx.y ? g_v : g_k;

    const int tid  = threadIdx.x;
    const int lane = tid & 31, wid = tid >> 5;
    const int wm = (wid & 3) * 32, wn = (wid >> 2) * 64;
    const int g = lane >> 2, t = lane & 3;

    float acc[2][8][4];
#pragma unroll
    for (int i = 0; i < 2; i++)
#pragma unroll
        for (int j = 0; j < 8; j++)
#pragma unroll
            for (int q = 0; q < 4; q++) acc[i][j][q] = 0.f;

    const int ac = tid & 7;
    float4 va[4];
#pragma unroll
    for (int i = 0; i < 4; i++) {
        int row = (tid + i * 256) >> 3;
        va[i] = *(const float4*)(tok + (size_t)(m0 + row) * CCAM + ac * 4);
    }

    for (int k0 = 0; k0 < CCAM; k0 += BK) {
#pragma unroll
        for (int i = 0; i < 4; i++) {
            int row = (tid + i * 256) >> 3;
            sA[row * SAW + ac * 2]     = f2b(va[i].x, va[i].y);
            sA[row * SAW + ac * 2 + 1] = f2b(va[i].z, va[i].w);
        }
#pragma unroll
        for (int i = 0; i < 4; i++) {
            int f = tid + i * 256, row = f >> 3, c = f & 7;
            float4 v = *(const float4*)(w + (size_t)row * CCAM + k0 + c * 4);
            sB[row * SAW + c * 2]     = f2b(v.x, v.y);
            sB[row * SAW + c * 2 + 1] = f2b(v.z, v.w);
        }
        __syncthreads();

        if (k0 + BK < CCAM) {
#pragma unroll
            for (int i = 0; i < 4; i++) {
                int row = (tid + i * 256) >> 3;
                va[i] = *(const float4*)(tok + (size_t)(m0 + row) * CCAM + (k0 + BK) + ac * 4);
            }
        }

#pragma unroll
        for (int kk = 0; kk < 2; kk++) {
            uint32_t br[8][2];
#pragma unroll
            for (int fn = 0; fn < 8; fn++) {
                int n = wn + fn * 8 + g;
                br[fn][0] = sB[n * SAW + kk * 8 + t];
                br[fn][1] = sB[n * SAW + kk * 8 + t + 4];
            }
#pragma unroll
            for (int fm = 0; fm < 2; fm++) {
                int m = wm + fm * 16 + g;
                uint32_t a0 = sA[m * SAW + kk * 8 + t];
                uint32_t a1 = sA[(m + 8) * SAW + kk * 8 + t];
                uint32_t a2 = sA[m * SAW + kk * 8 + t + 4];
                uint32_t a3 = sA[(m + 8) * SAW + kk * 8 + t + 4];
#pragma unroll
                for (int fn = 0; fn < 8; fn++)
                    MMA(acc[fm][fn], a0, a1, a2, a3, br[fn][0], br[fn][1]);
            }
        }
        __syncthreads();
    }

#pragma unroll
    for (int fm = 0; fm < 2; fm++)
#pragma unroll
        for (int fn = 0; fn < 8; fn++) {
            int m = m0 + wm + fm * 16 + g;
            int wcol = (wn >> 1) + fn * 4 + t;
            outp[(size_t)m * 64 + wcol]       = f2b(acc[fm][fn][0], acc[fm][fn][1]);
            outp[(size_t)(m + 8) * 64 + wcol] = f2b(acc[fm][fn][2], acc[fm][fn][3]);
        }
}

// ============================================================
// Kernel C: gathered Q GEMM + fused logit epilogue.
// 512 threads = 16 warps, warp grid 4(m) x 4(n), warp tile 32x32.
// Same BM=128 tile (same staging bytes as best version) but 2x warps
// per SM issuing gather loads -> latency hiding.
// ============================================================
__global__ void __launch_bounds__(512, 2)
k_qgemm(const float* __restrict__ lidar,
        const int*   __restrict__ ind,
        const float* __restrict__ q_w,
        const float* __restrict__ q_bias)
{
    __shared__ uint32_t sA[BM * SAW];
    __shared__ uint32_t sB[BN * SAW];
    __shared__ int spix[BM];

    const int m0    = blockIdx.x * BM;
    const int batch = m0 >> 13;
    const int tid   = threadIdx.x;

    if (tid < BM) {
        int tk = m0 + tid;
        int ii = ind[tk * 2 + 0], jj = ind[tk * 2 + 1];
        ii = min(max(ii, 0), HH - 1);
        jj = min(max(jj, 0), WW - 1);
        spix[tid] = ii * WW + jj;
    }
    __syncthreads();

    const int lane = tid & 31, wid = tid >> 5;
    const int wm = (wid & 3) * 32, wn = (wid >> 2) * 32;
    const int g = lane >> 2, t = lane & 3;

    float acc[2][4][4];
#pragma unroll
    for (int i = 0; i < 2; i++)
#pragma unroll
        for (int j = 0; j < 4; j++)
#pragma unroll
            for (int q = 0; q < 4; q++) acc[i][j][q] = 0.f;

    const float* lb = lidar + (size_t)batch * CLID * HWSZ;

    // hoist gather pixels (k0-invariant): 4 rows per thread
    int mypix[4];
#pragma unroll
    for (int i = 0; i < 4; i++) mypix[i] = spix[(tid + i * 512) >> 4];
    const int p = tid & 15;

    for (int k0 = 0; k0 < CLID; k0 += BK) {
#pragma unroll
        for (int i = 0; i < 4; i++) {           // gather: 128 rows x 16 wcols
            int row = (tid + i * 512) >> 4;
            const float* lp = lb + (size_t)(k0 + 2 * p) * HWSZ + mypix[i];
            sA[row * SAW + p] = f2b(lp[0], lp[HWSZ]);
        }
#pragma unroll
        for (int i = 0; i < 2; i++) {           // stage q_w (128 rows x 8 f4)
            int f = tid + i * 512, row = f >> 3, c = f & 7;
            float4 v = *(const float4*)(q_w + (size_t)row * CLID + k0 + c * 4);
            sB[row * SAW + c * 2]     = f2b(v.x, v.y);
            sB[row * SAW + c * 2 + 1] = f2b(v.z, v.w);
        }
        __syncthreads();
#pragma unroll
        for (int kk = 0; kk < 2; kk++) {
            uint32_t br[4][2];
#pragma unroll
            for (int fn = 0; fn < 4; fn++) {
                int n = wn + fn * 8 + g;
                br[fn][0] = sB[n * SAW + kk * 8 + t];
                br[fn][1] = sB[n * SAW + kk * 8 + t + 4];
            }
#pragma unroll
            for (int fm = 0; fm < 2; fm++) {
                int m = wm + fm * 16 + g;
                uint32_t a0 = sA[m * SAW + kk * 8 + t];
                uint32_t a1 = sA[(m + 8) * SAW + kk * 8 + t];
                uint32_t a2 = sA[m * SAW + kk * 8 + t + 4];
                uint32_t a3 = sA[(m + 8) * SAW + kk * 8 + t + 4];
#pragma unroll
                for (int fn = 0; fn < 4; fn++)
                    MMA(acc[fm][fn], a0, a1, a2, a3, br[fn][0], br[fn][1]);
            }
        }
        __syncthreads();
    }

    // fused logit epilogue: each warp owns head h = wn>>5 for rows wm..wm+31
    const int h = wn >> 5;
    float* lpo = g_logit + (size_t)(batch * NHEADS + h) * NTOK;
#pragma unroll
    for (int fm = 0; fm < 2; fm++) {
        int m = m0 + wm + fm * 16 + g;
        int tl0 = m & (NTOK - 1), tl1 = (m + 8) & (NTOK - 1);
        float p0 = 0.f, p1 = 0.f;
#pragma unroll
        for (int fn = 0; fn < 4; fn++) {
            int n0 = wn + fn * 8 + 2 * t;
            float2 qb = *(const float2*)(q_bias + n0);
            int word = (wn >> 1) + fn * 4 + t;
            float2 k0v = b2f(g_k[(size_t)m * 64 + word]);
            float2 k1v = b2f(g_k[(size_t)(m + 8) * 64 + word]);
            p0 += (acc[fm][fn][0] + qb.x) * k0v.x + (acc[fm][fn][1] + qb.y) * k0v.y;
            p1 += (acc[fm][fn][2] + qb.x) * k1v.x + (acc[fm][fn][3] + qb.y) * k1v.y;
        }
        p0 += __shfl_xor_sync(0xffffffffu, p0, 1);
        p0 += __shfl_xor_sync(0xffffffffu, p0, 2);
        p1 += __shfl_xor_sync(0xffffffffu, p1, 1);
        p1 += __shfl_xor_sync(0xffffffffu, p1, 2);
        if (t == 0) {
            lpo[tl0] = p0 * SCALE;
            lpo[tl1] = p1 * SCALE;
        }
    }
}

// ============================================================
// Kernel D: per (b,head,part) partial max + sumexp (grid = 64)
// ============================================================
__global__ void __launch_bounds__(256)
k_softred()
{
    const int bx  = blockIdx.x;
    const int bh  = bx >> 2, part = bx & 3;
    const float* lp = g_logit + (size_t)bh * NTOK + part * (NTOK / NPART);
    const int tid = threadIdx.x;
    __shared__ float red[256];

    float v[8];
#pragma unroll
    for (int i = 0; i < 8; i++) v[i] = lp[tid + i * 256];
    float mx = v[0];
#pragma unroll
    for (int i = 1; i < 8; i++) mx = fmaxf(mx, v[i]);
    red[tid] = mx; __syncthreads();
    for (int s = 128; s > 0; s >>= 1) {
        if (tid < s) red[tid] = fmaxf(red[tid], red[tid + s]);
        __syncthreads();
    }
    mx = red[0]; __syncthreads();

    float sum = 0.f;
#pragma unroll
    for (int i = 0; i < 8; i++) sum += expf(v[i] - mx);
    red[tid] = sum; __syncthreads();
    for (int s = 128; s > 0; s >>= 1) {
        if (tid < s) red[tid] += red[tid + s];
        __syncthreads();
    }
    if (tid == 0) g_part[bx] = make_float2(mx, red[0]);
}

// ============================================================
// Kernel E: k_fuse — attn weights; y = out_w @ (attn*V) -> g_y (dense)
// ============================================================
__global__ void __launch_bounds__(256, 2)
k_fuse(const float* __restrict__ gw,
       const float* __restrict__ alpha_p,
       const float* __restrict__ out_w)
{
    __shared__ uint32_t sA[BM * SAW];
    __shared__ uint32_t sB[BN * SAW];
    __shared__ float  saw_[BM * NHEADS];
    __shared__ float2 sred[NHEADS];

    const int m0    = blockIdx.x * BM;
    const int batch = m0 >> 13;
    const int tid   = threadIdx.x;

    if (tid < NHEADS) {
        int bh = batch * NHEADS + tid;
        float2 p[NPART];
#pragma unroll
        for (int i = 0; i < NPART; i++) p[i] = g_part[bh * NPART + i];
        float mx = p[0].x;
#pragma unroll
        for (int i = 1; i < NPART; i++) mx = fmaxf(mx, p[i].x);
        float sum = 0.f;
#pragma unroll
        for (int i = 0; i < NPART; i++) sum += p[i].y * expf(p[i].x - mx);
        sred[tid] = make_float2(mx, 1.0f / sum);
    }
    __syncthreads();
    {
        float alpha = *alpha_p;
#pragma unroll
        for (int j = 0; j < 2; j++) {
            int idx = tid + j * 256;
            int tl = idx & 127, h = idx >> 7;
            int tloc = (m0 & (NTOK - 1)) + tl;
            float  lt = g_logit[(size_t)(batch * NHEADS + h) * NTOK + tloc];
            float2 r  = sred[h];
            saw_[tl * NHEADS + h] = expf(lt - r.x) * r.y * gw[(size_t)batch * NTOK + tloc] * alpha;
        }
    }
    __syncthreads();

    const int lane = tid & 31, wid = tid >> 5;
    const int wm = (wid & 3) * 32, wn = (wid >> 2) * 64;
    const int g = lane >> 2, t = lane & 3;

    float acc[2][8][4];
#pragma unroll
    for (int i = 0; i < 2; i++)
#pragma unroll
        for (int j = 0; j < 8; j++)
#pragma unroll
            for (int q = 0; q < 4; q++) acc[i][j][q] = 0.f;

    for (int k0 = 0; k0 < HDIM; k0 += BK) {
#pragma unroll
        for (int i = 0; i < 8; i++) {
            int f = tid + i * 256, row = f >> 4, wc = f & 15;
            uint32_t u = g_v[(size_t)(m0 + row) * 64 + (k0 >> 1) + wc];
            float2 v = b2f(u);
            int h = (k0 + 2 * wc) >> 5;
            float wgt = saw_[row * NHEADS + h];
            sA[row * SAW + wc] = f2b(v.x * wgt, v.y * wgt);
        }
#pragma unroll
        for (int i = 0; i < 4; i++) {
            int f = tid + i * 256, row = f >> 3, c = f & 7;
            float4 v = *(const float4*)(out_w + (size_t)row * HDIM + k0 + c * 4);
            sB[row * SAW + c * 2]     = f2b(v.x, v.y);
            sB[row * SAW + c * 2 + 1] = f2b(v.z, v.w);
        }
        __syncthreads();
#pragma unroll
        for (int kk = 0; kk < 2; kk++) {
            uint32_t br[8][2];
#pragma unroll
            for (int fn = 0; fn < 8; fn++) {
                int n = wn + fn * 8 + g;
                br[fn][0] = sB[n * SAW + kk * 8 + t];
                br[fn][1] = sB[n * SAW + kk * 8 + t + 4];
            }
#pragma unroll
            for (int fm = 0; fm < 2; fm++) {
                int m = wm + fm * 16 + g;
                uint32_t a0 = sA[m * SAW + kk * 8 + t];
                uint32_t a1 = sA[(m + 8) * SAW + kk * 8 + t];
                uint32_t a2 = sA[m * SAW + kk * 8 + t + 4];
                uint32_t a3 = sA[(m + 8) * SAW + kk * 8 + t + 4];
#pragma unroll
                for (int fn = 0; fn < 8; fn++)
                    MMA(acc[fm][fn], a0, a1, a2, a3, br[fn][0], br[fn][1]);
            }
        }
        __syncthreads();
    }

#pragma unroll
    for (int fm = 0; fm < 2; fm++) {
        int m = m0 + wm + fm * 16 + g;
#pragma unroll
        for (int fn = 0; fn < 8; fn++) {
            int col = wn + fn * 8 + 2 * t;
            *(float2*)(g_y + (size_t)m * HDIM + col) =
                make_float2(acc[fm][fn][0], acc[fm][fn][1]);
            *(float2*)(g_y + (size_t)(m + 8) * HDIM + col) =
                make_float2(acc[fm][fn][2], acc[fm][fn][3]);
        }
    }
}

// ============================================================
// Kernel F: k_finalize — dense output pass, no atomics
// ============================================================
__global__ void __launch_bounds__(256)
k_finalize(const float* __restrict__ lidar,
           const float* __restrict__ alpha_p,
           const float* __restrict__ out_bias,
           float* __restrict__ out)
{
    __shared__ float sacc[32 * 129];
    __shared__ int   swork[32 * CAP];
    __shared__ int   stot;

    const int b   = blockIdx.x >> 11;
    const int p0  = (blockIdx.x & 2047) * 32;
    const int tid = threadIdx.x;

    for (int i = tid; i < 32 * 129; i += 256) sacc[i] = 0.f;

    if (tid < 32) {
        int px  = tid;
        int cnt = min(g_cnt[b * HWSZ + p0 + px], CAP);
        int inc = cnt;
#pragma unroll
        for (int d = 1; d < 32; d <<= 1) {
            int n = __shfl_up_sync(0xffffffffu, inc, d);
            if (px >= d) inc += n;
        }
        int excl = inc - cnt;
        if (px == 31) stot = inc;
        for (int i = 0; i < cnt; i++)
            swork[excl + i] = (px << 20) | g_list[(size_t)(b * HWSZ + p0 + px) * CAP + i];
    }
    __syncthreads();

    const int total = stot;
    for (int w = (tid >> 7); w < total; w += 2) {
        int e  = swork[w];
        int px = e >> 20, tk = e & 0xFFFFF;
        int c  = tid & 127;
        atomicAdd(&sacc[px * 129 + c], g_y[(size_t)tk * HDIM + c]);
    }
    __syncthreads();

    const float alpha = *alpha_p;
#pragma unroll
    for (int j = 0; j < 16; j++) {
        int lin = tid + j * 256;
        int c = lin >> 5, px = lin & 31;
        size_t gi = ((size_t)b * CLID + c) * HWSZ + p0 + px;
        out[gi] = lidar[gi] + alpha * out_bias[c] + sacc[px * 129 + c];
    }
}

// ============================================================
// Kernel G: k_ovf — overflow tokens (grid-stride; normally zero work)
// ============================================================
__global__ void __launch_bounds__(256)
k_ovf(const int* __restrict__ ind,
      float* __restrict__ out)
{
    __shared__ int scnt;
    if (threadIdx.x == 0) scnt = g_ovfc;
    __syncthreads();
    const int nw = scnt * 8;
    for (int idx = blockIdx.x * 256 + threadIdx.x; idx < nw; idx += 32 * 256) {
        int o  = idx >> 3;
        int tk = g_ovf[o];
        int c0 = (idx & 7) * 16;
        int b  = tk >> 13;
        int ii = ind[tk * 2 + 0], jj = ind[tk * 2 + 1];
        ii = min(max(ii, 0), HH - 1);
        jj = min(max(jj, 0), WW - 1);
        int pix = ii * WW + jj;
        const float* yp = g_y + (size_t)tk * HDIM + c0;
        float* ob = out + (size_t)b * CLID * HWSZ + (size_t)c0 * HWSZ + pix;
#pragma unroll
        for (int c = 0; c < 16; c++)
            atomicAdd(ob + (size_t)c * HWSZ, yp[c]);
    }
}

// ============================================================
extern "C" void kernel_launch(void* const* d_in, const int* in_sizes, int n_in,
                              void* d_out, int out_size)
{
    const float* lidar = (const float*)d_in[0];
    const float* tok   = (const float*)d_in[1];
    const int*   ind   = (const int*)  d_in[2];
    const float* gw    = (const float*)d_in[3];
    const float* alpha = (const float*)d_in[4];
    const float* q_w   = (const float*)d_in[5];
    const float* q_b   = (const float*)d_in[6];
    const float* k_w   = (const float*)d_in[7];
    const float* v_w   = (const float*)d_in[8];
    const float* o_w   = (const float*)d_in[9];
    const float* o_b   = (const float*)d_in[10];
    float* out = (float*)d_out;

    k_zero<<<BB * HWSZ / 4 / 256, 256>>>();
    k_bin<<<MTOT / 256, 256>>>(ind);
    dim3 gb(NT128, 2);
    k_kv<<<gb, 256>>>(tok, k_w, v_w);
    k_qgemm<<<NT128, 512>>>(lidar, ind, q_w, q_b);
    k_softred<<<BB * NHEADS * NPART, 256>>>();
    k_fuse<<<NT128, 256>>>(gw, alpha, o_w);
    k_finalize<<<BB * HWSZ / 32, 256>>>(lidar, alpha, o_b, out);
    k_ovf<<<32, 256>>>(ind, out);
}